// round 1
// baseline (speedup 1.0000x reference)
#include <cuda_runtime.h>
#include <cuda_bf16.h>

// Problem constants
#define B_SZ   2
#define T_SZ   2048
#define C_SZ   1024
#define H_SZ   16
#define D_SZ   64
#define M_ROWS (B_SZ * T_SZ)      // 4096
#define N_QKV  (3 * C_SZ)         // 3072

// Scratch (allocation-free rule: __device__ globals)
__device__ float g_k[B_SZ * H_SZ * T_SZ * D_SZ];     // [B,H,T,D] 16MB
__device__ float g_q[B_SZ * H_SZ * T_SZ * D_SZ];
__device__ float g_v[B_SZ * H_SZ * T_SZ * D_SZ];
__device__ float g_attn[B_SZ * T_SZ * C_SZ];         // [B,T,C]  16MB

// ---------------------------------------------------------------------------
// Kernel 1: QKV GEMM  kqv = x @ W + b, scattered into k/q/v [B,H,T,D] buffers
// 128x128 tile, BK=8, 256 threads, 8x8 per-thread
// ---------------------------------------------------------------------------
__global__ __launch_bounds__(256)
void qkv_gemm_kernel(const float* __restrict__ x,
                     const float* __restrict__ w,
                     const float* __restrict__ bias) {
    __shared__ float As[8][128];
    __shared__ float Bs[8][128];

    const int tid = threadIdx.x;
    const int tx = tid & 15;          // 0..15
    const int ty = tid >> 4;          // 0..15
    const int rowBase = blockIdx.y * 128;
    const int colBase = blockIdx.x * 128;
    const int K = C_SZ;               // 1024
    const int N = N_QKV;              // 3072

    float acc[8][8];
#pragma unroll
    for (int i = 0; i < 8; i++)
#pragma unroll
        for (int j = 0; j < 8; j++) acc[i][j] = 0.f;

    const int aRow = tid >> 1;            // 0..127
    const int aCol = (tid & 1) * 4;       // 0 or 4
    const int bRow = tid >> 5;            // 0..7
    const int bCol = (tid & 31) * 4;      // 0..124

    for (int kk = 0; kk < K; kk += 8) {
        float4 a4 = *(const float4*)(x + (size_t)(rowBase + aRow) * K + kk + aCol);
        As[aCol + 0][aRow] = a4.x;
        As[aCol + 1][aRow] = a4.y;
        As[aCol + 2][aRow] = a4.z;
        As[aCol + 3][aRow] = a4.w;
        float4 b4 = *(const float4*)(w + (size_t)(kk + bRow) * N + colBase + bCol);
        *(float4*)&Bs[bRow][bCol] = b4;
        __syncthreads();

#pragma unroll
        for (int k = 0; k < 8; k++) {
            float4 ra0 = *(float4*)&As[k][ty * 8];
            float4 ra1 = *(float4*)&As[k][ty * 8 + 4];
            float4 rb0 = *(float4*)&Bs[k][tx * 8];
            float4 rb1 = *(float4*)&Bs[k][tx * 8 + 4];
            float ra[8] = {ra0.x, ra0.y, ra0.z, ra0.w, ra1.x, ra1.y, ra1.z, ra1.w};
            float rb[8] = {rb0.x, rb0.y, rb0.z, rb0.w, rb1.x, rb1.y, rb1.z, rb1.w};
#pragma unroll
            for (int i = 0; i < 8; i++)
#pragma unroll
                for (int j = 0; j < 8; j++) acc[i][j] += ra[i] * rb[j];
        }
        __syncthreads();
    }

    // Epilogue: bias + scatter into k/q/v [B,H,T,D]
#pragma unroll
    for (int i = 0; i < 8; i++) {
        const int m = rowBase + ty * 8 + i;
        const int b = m >> 11;            // /2048
        const int t = m & 2047;
#pragma unroll
        for (int j = 0; j < 8; j++) {
            const int n = colBase + tx * 8 + j;
            float val = acc[i][j] + bias[n];
            const int sec = n >> 10;      // 0:k 1:q 2:v
            const int c = n & 1023;
            const int h = c >> 6;
            const int d = c & 63;
            float* dst = (sec == 0) ? g_k : (sec == 1) ? g_q : g_v;
            dst[(((size_t)(b * H_SZ + h) * T_SZ) + t) * D_SZ + d] = val;
        }
    }
}

// ---------------------------------------------------------------------------
// Kernel 2: causal attention (flash-style streaming softmax)
// Source convention: wei[i][j] = k_i . q_j  -> query-role = k, key-role = q
// Block: 64 rows of one (b,h); 256 threads; quad (4 threads) per row.
// Thread (r,c) owns j,d in {c, c+4, c+8, ...} (stride-4 interleave -> no smem
// bank conflicts on the score / PV inner loops).
// ---------------------------------------------------------------------------
#define ATT_SMEM_FLOATS (4 * 64 * 65)
__global__ __launch_bounds__(256)
void attn_kernel() {
    extern __shared__ float sm[];
    float* Qs = sm;                // [64][65]  query-role tile (rows of g_k)
    float* Ks = sm + 64 * 65;      // [64][65]  key-role tile  (rows of g_q)
    float* Vs = sm + 2 * 64 * 65;  // [64][65]
    float* Ss = sm + 3 * 64 * 65;  // [64][65]  probabilities

    const int bh = blockIdx.x;     // 0..31
    const int ri = blockIdx.y;     // row tile 0..31
    const int tid = threadIdx.x;
    const int r = tid >> 2;        // 0..63 row within tile
    const int c = tid & 3;         // 0..3 quad lane

    const float* Qp = g_k + (size_t)bh * T_SZ * D_SZ;   // swapped roles
    const float* Kp = g_q + (size_t)bh * T_SZ * D_SZ;
    const float* Vp = g_v + (size_t)bh * T_SZ * D_SZ;

    // load Q tile
    for (int idx = tid; idx < 64 * 64; idx += 256) {
        int rr = idx >> 6, dd = idx & 63;
        Qs[rr * 65 + dd] = Qp[(size_t)(ri * 64 + rr) * 64 + dd];
    }

    const int i_global = ri * 64 + r;
    const float scale = 0.125f;    // 1/sqrt(64)
    float m_i = -1e30f, l_i = 0.f;
    float o[16];
#pragma unroll
    for (int dd = 0; dd < 16; dd++) o[dd] = 0.f;

    for (int jt = 0; jt <= ri; jt++) {
        __syncthreads();
        for (int idx = tid; idx < 64 * 64; idx += 256) {
            int rr = idx >> 6, dd = idx & 63;
            Ks[rr * 65 + dd] = Kp[(size_t)(jt * 64 + rr) * 64 + dd];
            Vs[rr * 65 + dd] = Vp[(size_t)(jt * 64 + rr) * 64 + dd];
        }
        __syncthreads();

        // scores for my 16 j's: j_local = 4*jj + c
        float s[16];
#pragma unroll
        for (int jj = 0; jj < 16; jj++) s[jj] = 0.f;
        for (int d = 0; d < 64; d++) {
            float qd = Qs[r * 65 + d];
#pragma unroll
            for (int jj = 0; jj < 16; jj++)
                s[jj] += qd * Ks[(4 * jj + c) * 65 + d];
        }
        // scale + causal mask
        float rowmax = -1e30f;
#pragma unroll
        for (int jj = 0; jj < 16; jj++) {
            int j = jt * 64 + 4 * jj + c;
            s[jj] = (j <= i_global) ? s[jj] * scale : -1e30f;
            rowmax = fmaxf(rowmax, s[jj]);
        }
        rowmax = fmaxf(rowmax, __shfl_xor_sync(0xffffffffu, rowmax, 1));
        rowmax = fmaxf(rowmax, __shfl_xor_sync(0xffffffffu, rowmax, 2));
        float m_new = fmaxf(m_i, rowmax);
        float p_sum = 0.f;
#pragma unroll
        for (int jj = 0; jj < 16; jj++) {
            s[jj] = __expf(s[jj] - m_new);
            p_sum += s[jj];
        }
        p_sum += __shfl_xor_sync(0xffffffffu, p_sum, 1);
        p_sum += __shfl_xor_sync(0xffffffffu, p_sum, 2);
        float alpha = __expf(m_i - m_new);
        l_i = l_i * alpha + p_sum;
        m_i = m_new;
#pragma unroll
        for (int dd = 0; dd < 16; dd++) o[dd] *= alpha;

        // stash p in smem (row-local, warp-local -> syncwarp suffices)
#pragma unroll
        for (int jj = 0; jj < 16; jj++)
            Ss[r * 65 + 4 * jj + c] = s[jj];
        __syncwarp();

        // PV: my 16 d's are d = 4*dd + c
        for (int j = 0; j < 64; j++) {
            float p = Ss[r * 65 + j];
#pragma unroll
            for (int dd = 0; dd < 16; dd++)
                o[dd] += p * Vs[j * 65 + 4 * dd + c];
        }
        __syncwarp();
    }

    const float inv = 1.f / l_i;
    const int b = bh >> 4;         // /16
    const int h = bh & 15;
    float* op = g_attn + ((size_t)(b * T_SZ + i_global) * C_SZ) + h * D_SZ;
#pragma unroll
    for (int dd = 0; dd < 16; dd++)
        op[4 * dd + c] = o[dd] * inv;
}

// ---------------------------------------------------------------------------
// Kernel 3: output projection  out = attn @ Wp + bp   (4096x1024x1024)
// ---------------------------------------------------------------------------
__global__ __launch_bounds__(256)
void proj_gemm_kernel(const float* __restrict__ w,
                      const float* __restrict__ bias,
                      float* __restrict__ out) {
    __shared__ float As[8][128];
    __shared__ float Bs[8][128];

    const int tid = threadIdx.x;
    const int tx = tid & 15;
    const int ty = tid >> 4;
    const int rowBase = blockIdx.y * 128;
    const int colBase = blockIdx.x * 128;
    const int K = C_SZ;   // 1024
    const int N = C_SZ;   // 1024
    const float* x = g_attn;

    float acc[8][8];
#pragma unroll
    for (int i = 0; i < 8; i++)
#pragma unroll
        for (int j = 0; j < 8; j++) acc[i][j] = 0.f;

    const int aRow = tid >> 1;
    const int aCol = (tid & 1) * 4;
    const int bRow = tid >> 5;
    const int bCol = (tid & 31) * 4;

    for (int kk = 0; kk < K; kk += 8) {
        float4 a4 = *(const float4*)(x + (size_t)(rowBase + aRow) * K + kk + aCol);
        As[aCol + 0][aRow] = a4.x;
        As[aCol + 1][aRow] = a4.y;
        As[aCol + 2][aRow] = a4.z;
        As[aCol + 3][aRow] = a4.w;
        float4 b4 = *(const float4*)(w + (size_t)(kk + bRow) * N + colBase + bCol);
        *(float4*)&Bs[bRow][bCol] = b4;
        __syncthreads();

#pragma unroll
        for (int k = 0; k < 8; k++) {
            float4 ra0 = *(float4*)&As[k][ty * 8];
            float4 ra1 = *(float4*)&As[k][ty * 8 + 4];
            float4 rb0 = *(float4*)&Bs[k][tx * 8];
            float4 rb1 = *(float4*)&Bs[k][tx * 8 + 4];
            float ra[8] = {ra0.x, ra0.y, ra0.z, ra0.w, ra1.x, ra1.y, ra1.z, ra1.w};
            float rb[8] = {rb0.x, rb0.y, rb0.z, rb0.w, rb1.x, rb1.y, rb1.z, rb1.w};
#pragma unroll
            for (int i = 0; i < 8; i++)
#pragma unroll
                for (int j = 0; j < 8; j++) acc[i][j] += ra[i] * rb[j];
        }
        __syncthreads();
    }

#pragma unroll
    for (int i = 0; i < 8; i++) {
        const int m = rowBase + ty * 8 + i;
#pragma unroll
        for (int j = 0; j < 8; j++) {
            const int n = colBase + tx * 8 + j;
            out[(size_t)m * N + n] = acc[i][j] + bias[n];
        }
    }
}

// ---------------------------------------------------------------------------
extern "C" void kernel_launch(void* const* d_in, const int* in_sizes, int n_in,
                              void* d_out, int out_size) {
    const float* x        = (const float*)d_in[0];   // [2,2048,1024]
    const float* c_attn_w = (const float*)d_in[1];   // [1024,3072]
    const float* c_attn_b = (const float*)d_in[2];   // [3072]
    const float* c_proj_w = (const float*)d_in[3];   // [1024,1024]
    const float* c_proj_b = (const float*)d_in[4];   // [1024]
    float* out = (float*)d_out;

    // QKV GEMM: grid (N/128, M/128) = (24, 32)
    {
        dim3 grid(N_QKV / 128, M_ROWS / 128);
        qkv_gemm_kernel<<<grid, 256>>>(x, c_attn_w, c_attn_b);
    }

    // Attention: grid (B*H, T/64) = (32, 32), 66,560 B dynamic smem
    {
        const int smemBytes = ATT_SMEM_FLOATS * (int)sizeof(float);
        cudaFuncSetAttribute(attn_kernel,
                             cudaFuncAttributeMaxDynamicSharedMemorySize, smemBytes);
        dim3 grid(B_SZ * H_SZ, T_SZ / 64);
        attn_kernel<<<grid, 256, smemBytes>>>();
    }

    // Proj GEMM: grid (8, 32)
    {
        dim3 grid(C_SZ / 128, M_ROWS / 128);
        proj_gemm_kernel<<<grid, 256>>>(c_proj_w, c_proj_b, out);
    }
}

// round 3
// speedup vs baseline: 2.2669x; 2.2669x over previous
#include <cuda_runtime.h>
#include <cuda_bf16.h>
#include <cstdint>

// Problem constants
#define B_SZ   2
#define T_SZ   2048
#define C_SZ   1024
#define H_SZ   16
#define D_SZ   64
#define M_ROWS 4096
#define N_QKV  3072
#define GEMM_K 1024

// ---------------------------------------------------------------------------
// Scratch (__device__ globals; no allocation allowed)
// ---------------------------------------------------------------------------
__device__ float g_k[32 * T_SZ * D_SZ];   // [b*16+h][t][d] fp32 for attention
__device__ float g_q[32 * T_SZ * D_SZ];
__device__ float g_v[32 * T_SZ * D_SZ];
__device__ __nv_bfloat16 g_x_hi[M_ROWS * C_SZ];
__device__ __nv_bfloat16 g_x_lo[M_ROWS * C_SZ];
__device__ __nv_bfloat16 g_wq_hi[N_QKV * GEMM_K];   // transposed [n][k]
__device__ __nv_bfloat16 g_wq_lo[N_QKV * GEMM_K];
__device__ __nv_bfloat16 g_wp_hi[C_SZ * GEMM_K];    // transposed [n][k]
__device__ __nv_bfloat16 g_wp_lo[C_SZ * GEMM_K];
__device__ __nv_bfloat16 g_ao_hi[M_ROWS * C_SZ];    // attention out split
__device__ __nv_bfloat16 g_ao_lo[M_ROWS * C_SZ];

// ---------------------------------------------------------------------------
// PTX helpers (all valid on plain sm_103 PTX target: no 'a'-suffix features)
// ---------------------------------------------------------------------------
#define CP_ASYNC8(dst, src) \
    asm volatile("cp.async.ca.shared.global [%0], [%1], 8;" :: "r"(dst), "l"(src))
#define CP_COMMIT() asm volatile("cp.async.commit_group;" ::: "memory")
#define CP_WAIT1()  asm volatile("cp.async.wait_group 1;" ::: "memory")
#define CP_WAIT0()  asm volatile("cp.async.wait_group 0;" ::: "memory")

__device__ __forceinline__ void ldm_x4(uint32_t* r, uint32_t a) {
    asm volatile("ldmatrix.sync.aligned.m8n8.x4.shared.b16 {%0,%1,%2,%3}, [%4];"
                 : "=r"(r[0]), "=r"(r[1]), "=r"(r[2]), "=r"(r[3]) : "r"(a));
}

__device__ __forceinline__ void mma_bf16(float* d, const uint32_t* a,
                                         const uint32_t* b) {
    asm volatile(
        "mma.sync.aligned.m16n8k16.row.col.f32.bf16.bf16.f32 "
        "{%0,%1,%2,%3}, {%4,%5,%6,%7}, {%8,%9}, {%0,%1,%2,%3};"
        : "+f"(d[0]), "+f"(d[1]), "+f"(d[2]), "+f"(d[3])
        : "r"(a[0]), "r"(a[1]), "r"(a[2]), "r"(a[3]), "r"(b[0]), "r"(b[1]));
}

// ---------------------------------------------------------------------------
// Split kernels: fp32 -> (hi, lo) bf16
// ---------------------------------------------------------------------------
__global__ __launch_bounds__(256)
void split_x_kernel(const float* __restrict__ in) {
    int i = blockIdx.x * 256 + threadIdx.x;          // grid covers 4M exactly
    float v = in[i];
    __nv_bfloat16 h = __float2bfloat16(v);
    g_x_hi[i] = h;
    g_x_lo[i] = __float2bfloat16(v - __bfloat162float(h));
}

// w [K][N] fp32 -> out [N][K] bf16 hi/lo (transpose + split)
__global__ void tsplit_kernel(const float* __restrict__ w, int N, int mode) {
    __shared__ float tile[32][33];
    const int nb = blockIdx.x * 32, kb = blockIdx.y * 32;
    const int tx = threadIdx.x, ty = threadIdx.y;   // (32, 8)
#pragma unroll
    for (int i2 = 0; i2 < 32; i2 += 8)
        tile[ty + i2][tx] = w[(size_t)(kb + ty + i2) * N + nb + tx];
    __syncthreads();
    __nv_bfloat16* oh = mode ? g_wp_hi : g_wq_hi;
    __nv_bfloat16* ol = mode ? g_wp_lo : g_wq_lo;
#pragma unroll
    for (int i2 = 0; i2 < 32; i2 += 8) {
        float v = tile[tx][ty + i2];                 // = w[kb+tx][nb+ty+i2]
        __nv_bfloat16 h = __float2bfloat16(v);
        size_t o = (size_t)(nb + ty + i2) * GEMM_K + kb + tx;
        oh[o] = h;
        ol[o] = __float2bfloat16(v - __bfloat162float(h));
    }
}

// ---------------------------------------------------------------------------
// HMMA split-bf16 GEMM: C[128,128] fp32 = (Ah+Al) @ (Bh+Bl)^T  (3 passes)
// Block 256 threads = 8 warps (4 m-rows x 2 n-cols); warp tile 32x64.
// BK=32, cp.async double buffered. Smem rows padded to 80B (conflict-free
// ldmatrix: row addrs i*80B -> i*5 (16B units) mod 8 cycles through all banks).
// mode 0: A=x(split), B=wqkv^T(split); epilogue bias + scatter k/q/v fp32
// mode 1: A=attn out(split), B=wproj^T(split); epilogue bias + store out
// ---------------------------------------------------------------------------
#define AS_BF16 40                       // padded row stride in bf16 (80 B)
#define TILE_B  (128 * AS_BF16 * 2)      // 10240 B per matrix variant
#define GEMM_SMEM (2 * 4 * TILE_B)       // 81920 B

__global__ __launch_bounds__(256, 1)
void gemm_hmma(const float* __restrict__ bias, float* __restrict__ out,
               int mode) {
    extern __shared__ char smem[];
    const uint32_t sbase = (uint32_t)__cvta_generic_to_shared(smem);
    const int tid = threadIdx.x;
    const int lane = tid & 31, warp = tid >> 5;
    const int wr = warp & 3, wc = warp >> 2;
    const int rowBase = blockIdx.y * 128;
    const int colBase = blockIdx.x * 128;

    const __nv_bfloat16 *srcs[4];
    if (mode == 0) { srcs[0] = g_x_hi;  srcs[1] = g_x_lo;  srcs[2] = g_wq_hi; srcs[3] = g_wq_lo; }
    else           { srcs[0] = g_ao_hi; srcs[1] = g_ao_lo; srcs[2] = g_wp_hi; srcs[3] = g_wp_lo; }
    const int bases[4] = {rowBase, rowBase, colBase, colBase};

    float acc[2][8][4];
#pragma unroll
    for (int mt = 0; mt < 2; mt++)
#pragma unroll
        for (int nt = 0; nt < 8; nt++)
#pragma unroll
            for (int q = 0; q < 4; q++) acc[mt][nt][q] = 0.f;

    // prefetch: per variant tile, 1024 8B pieces; thread does 4
    auto prefetch = [&](int chunk) {
        const int buf = chunk & 1;
        const int k0 = chunk * 32;
#pragma unroll
        for (int w = 0; w < 4; w++) {
#pragma unroll
            for (int it = 0; it < 4; it++) {
                int p = tid + it * 256;
                int r = p >> 3, cp = p & 7;
                const __nv_bfloat16* g =
                    srcs[w] + (size_t)(bases[w] + r) * GEMM_K + k0 + cp * 4;
                uint32_t d = sbase + (uint32_t)(buf * 4 * TILE_B + w * TILE_B
                                                + r * 80 + cp * 8);
                CP_ASYNC8(d, g);
            }
        }
        CP_COMMIT();
    };

    prefetch(0);

    const int NC = GEMM_K / 32;          // 32
    for (int c = 0; c < NC; c++) {
        if (c + 1 < NC) { prefetch(c + 1); CP_WAIT1(); }
        else            { CP_WAIT0(); }
        __syncthreads();

        const uint32_t bufBase = sbase + (uint32_t)((c & 1) * 4 * TILE_B);
        const uint32_t ahB = bufBase;
        const uint32_t alB = bufBase + TILE_B;
        const uint32_t bhB = bufBase + 2 * TILE_B;
        const uint32_t blB = bufBase + 3 * TILE_B;

#pragma unroll
        for (int s = 0; s < 2; s++) {
            uint32_t ah[2][4], al[2][4], bh[4][4], bl[4][4];
            const int akb = s * 32 + ((lane >> 4) & 1) * 16;
            const int arow = wr * 32 + (lane & 7) + ((lane >> 3) & 1) * 8;
            ldm_x4(ah[0], ahB + (uint32_t)(arow * 80 + akb));
            ldm_x4(ah[1], ahB + (uint32_t)((arow + 16) * 80 + akb));
            ldm_x4(al[0], alB + (uint32_t)(arow * 80 + akb));
            ldm_x4(al[1], alB + (uint32_t)((arow + 16) * 80 + akb));

            const int bkb = s * 32 + ((lane >> 3) & 1) * 16;
            const int brow = wc * 64 + ((lane >> 4) & 1) * 8 + (lane & 7);
#pragma unroll
            for (int p2 = 0; p2 < 4; p2++) {
                ldm_x4(bh[p2], bhB + (uint32_t)((brow + p2 * 16) * 80 + bkb));
                ldm_x4(bl[p2], blB + (uint32_t)((brow + p2 * 16) * 80 + bkb));
            }

#pragma unroll
            for (int mt = 0; mt < 2; mt++)
#pragma unroll
                for (int nt = 0; nt < 8; nt++) {
                    const uint32_t* bhf = &bh[nt >> 1][(nt & 1) * 2];
                    const uint32_t* blf = &bl[nt >> 1][(nt & 1) * 2];
                    mma_bf16(acc[mt][nt], ah[mt], bhf);
                    mma_bf16(acc[mt][nt], ah[mt], blf);
                    mma_bf16(acc[mt][nt], al[mt], bhf);
                }
        }
        __syncthreads();
    }

    // Epilogue: thread (lane) covers rows r0,r0+8, cols c0,c0+1 per tile
    const int r0 = lane >> 2;
    const int c0 = (lane & 3) * 2;
#pragma unroll
    for (int mt = 0; mt < 2; mt++) {
#pragma unroll
        for (int nt = 0; nt < 8; nt++) {
            const int n0 = colBase + wc * 64 + nt * 8 + c0;
            const float b0 = bias[n0], b1 = bias[n0 + 1];
#pragma unroll
            for (int half = 0; half < 2; half++) {
                const int m = rowBase + wr * 32 + mt * 16 + r0 + half * 8;
                float2 v;
                v.x = acc[mt][nt][half * 2 + 0] + b0;
                v.y = acc[mt][nt][half * 2 + 1] + b1;
                if (mode == 0) {
                    const int bb = m >> 11, t = m & 2047;
                    const int sec = n0 >> 10, cc = n0 & 1023;
                    const int h = cc >> 6, d0 = cc & 63;
                    float* dst = (sec == 0 ? g_k : sec == 1 ? g_q : g_v);
                    *(float2*)(dst + (((size_t)(bb * 16 + h)) * T_SZ + t) * 64 + d0) = v;
                } else {
                    *(float2*)(out + (size_t)m * C_SZ + n0) = v;
                }
            }
        }
    }
}

// ---------------------------------------------------------------------------
// Attention: fp32 flash, 4x4 register blocking, 64x64 tiles.
// Source convention: wei = K@Q^T -> query-role = g_k, key-role = g_q.
// Writes output directly as bf16 hi/lo for the proj GEMM.
// ---------------------------------------------------------------------------
#define QK_STRIDE 72   // float stride, 16B-aligned float4 rows
#define PT_STRIDE 65
#define ATT2_SMEM ((3 * 64 * QK_STRIDE + 64 * PT_STRIDE) * 4)

__global__ __launch_bounds__(256)
void attn_kernel2() {
    extern __shared__ float sm[];
    float* Qt = sm;                        // [d][i] transposed
    float* Kt = Qt + 64 * QK_STRIDE;       // [d][j] transposed
    float* Vs = Kt + 64 * QK_STRIDE;       // [j][d] natural
    float* Pt = Vs + 64 * QK_STRIDE;       // [j][i]

    const int bh = blockIdx.x;             // b*16+h
    const int ri = blockIdx.y;             // i-tile
    const int tid = threadIdx.x;
    const int tx = tid & 15, ty = tid >> 4;

    const float* Qp = g_k + (size_t)bh * T_SZ * D_SZ;   // swapped roles
    const float* Kp = g_q + (size_t)bh * T_SZ * D_SZ;
    const float* Vp = g_v + (size_t)bh * T_SZ * D_SZ;

    for (int idx = tid; idx < 4096; idx += 256) {
        int t = idx >> 6, d = idx & 63;
        Qt[d * QK_STRIDE + t] = Qp[(size_t)(ri * 64 + t) * 64 + d];
    }

    float m_i[4], l_i[4], o[4][4];
#pragma unroll
    for (int ii = 0; ii < 4; ii++) {
        m_i[ii] = -1e30f; l_i[ii] = 0.f;
#pragma unroll
        for (int dd = 0; dd < 4; dd++) o[ii][dd] = 0.f;
    }

    for (int jt = 0; jt <= ri; jt++) {
        __syncthreads();
        for (int idx = tid; idx < 4096; idx += 256) {
            int t = idx >> 6, d = idx & 63;
            float kv = Kp[(size_t)(jt * 64 + t) * 64 + d];
            float vv = Vp[(size_t)(jt * 64 + t) * 64 + d];
            Kt[d * QK_STRIDE + t] = kv;
            Vs[t * QK_STRIDE + d] = vv;
        }
        __syncthreads();

        float s[4][4];
#pragma unroll
        for (int ii = 0; ii < 4; ii++)
#pragma unroll
            for (int jj = 0; jj < 4; jj++) s[ii][jj] = 0.f;

#pragma unroll 8
        for (int d = 0; d < 64; d++) {
            float4 a4 = *(float4*)&Qt[d * QK_STRIDE + ty * 4];
            float4 b4 = *(float4*)&Kt[d * QK_STRIDE + tx * 4];
            float av[4] = {a4.x, a4.y, a4.z, a4.w};
            float bv[4] = {b4.x, b4.y, b4.z, b4.w};
#pragma unroll
            for (int ii = 0; ii < 4; ii++)
#pragma unroll
                for (int jj = 0; jj < 4; jj++) s[ii][jj] += av[ii] * bv[jj];
        }

#pragma unroll
        for (int ii = 0; ii < 4; ii++) {
            const int ig = ri * 64 + ty * 4 + ii;
            float rmax = -1e30f;
#pragma unroll
            for (int jj = 0; jj < 4; jj++) {
                int j = jt * 64 + tx * 4 + jj;
                s[ii][jj] = (j <= ig) ? s[ii][jj] * 0.125f : -1e30f;
                rmax = fmaxf(rmax, s[ii][jj]);
            }
            rmax = fmaxf(rmax, __shfl_xor_sync(0xffffffffu, rmax, 1));
            rmax = fmaxf(rmax, __shfl_xor_sync(0xffffffffu, rmax, 2));
            rmax = fmaxf(rmax, __shfl_xor_sync(0xffffffffu, rmax, 4));
            rmax = fmaxf(rmax, __shfl_xor_sync(0xffffffffu, rmax, 8));
            float mn = fmaxf(m_i[ii], rmax);
            float al = __expf(m_i[ii] - mn);
            float ps = 0.f;
#pragma unroll
            for (int jj = 0; jj < 4; jj++) {
                s[ii][jj] = __expf(s[ii][jj] - mn);
                ps += s[ii][jj];
            }
            ps += __shfl_xor_sync(0xffffffffu, ps, 1);
            ps += __shfl_xor_sync(0xffffffffu, ps, 2);
            ps += __shfl_xor_sync(0xffffffffu, ps, 4);
            ps += __shfl_xor_sync(0xffffffffu, ps, 8);
            l_i[ii] = l_i[ii] * al + ps;
            m_i[ii] = mn;
#pragma unroll
            for (int dd = 0; dd < 4; dd++) o[ii][dd] *= al;
#pragma unroll
            for (int jj = 0; jj < 4; jj++)
                Pt[(tx * 4 + jj) * PT_STRIDE + ty * 4 + ii] = s[ii][jj];
        }
        __syncthreads();

#pragma unroll 8
        for (int j = 0; j < 64; j++) {
            float p0 = Pt[j * PT_STRIDE + ty * 4 + 0];
            float p1 = Pt[j * PT_STRIDE + ty * 4 + 1];
            float p2 = Pt[j * PT_STRIDE + ty * 4 + 2];
            float p3 = Pt[j * PT_STRIDE + ty * 4 + 3];
            float4 v4 = *(float4*)&Vs[j * QK_STRIDE + tx * 4];
            float vv[4] = {v4.x, v4.y, v4.z, v4.w};
#pragma unroll
            for (int dd = 0; dd < 4; dd++) {
                o[0][dd] += p0 * vv[dd];
                o[1][dd] += p1 * vv[dd];
                o[2][dd] += p2 * vv[dd];
                o[3][dd] += p3 * vv[dd];
            }
        }
    }

    const int b = bh >> 4, h = bh & 15;
#pragma unroll
    for (int ii = 0; ii < 4; ii++) {
        const int t = ri * 64 + ty * 4 + ii;
        const float inv = 1.f / l_i[ii];
        const size_t base = ((size_t)(b * T_SZ + t)) * C_SZ + h * 64 + tx * 4;
#pragma unroll
        for (int dd = 0; dd < 4; dd++) {
            float v = o[ii][dd] * inv;
            __nv_bfloat16 hi = __float2bfloat16(v);
            g_ao_hi[base + dd] = hi;
            g_ao_lo[base + dd] = __float2bfloat16(v - __bfloat162float(hi));
        }
    }
}

// ---------------------------------------------------------------------------
extern "C" void kernel_launch(void* const* d_in, const int* in_sizes, int n_in,
                              void* d_out, int out_size) {
    const float* x        = (const float*)d_in[0];   // [2,2048,1024]
    const float* c_attn_w = (const float*)d_in[1];   // [1024,3072]
    const float* c_attn_b = (const float*)d_in[2];   // [3072]
    const float* c_proj_w = (const float*)d_in[3];   // [1024,1024]
    const float* c_proj_b = (const float*)d_in[4];   // [1024]
    float* out = (float*)d_out;

    // Split / transpose prep
    split_x_kernel<<<(M_ROWS * C_SZ) / 256, 256>>>(x);
    tsplit_kernel<<<dim3(N_QKV / 32, GEMM_K / 32), dim3(32, 8)>>>(c_attn_w, N_QKV, 0);
    tsplit_kernel<<<dim3(C_SZ / 32, GEMM_K / 32), dim3(32, 8)>>>(c_proj_w, C_SZ, 1);

    cudaFuncSetAttribute(gemm_hmma,
                         cudaFuncAttributeMaxDynamicSharedMemorySize, GEMM_SMEM);

    // QKV GEMM (HMMA split-bf16): grid (24, 32)
    gemm_hmma<<<dim3(N_QKV / 128, M_ROWS / 128), 256, GEMM_SMEM>>>(
        c_attn_b, nullptr, 0);

    // Attention (fp32, 4x4 register blocking)
    cudaFuncSetAttribute(attn_kernel2,
                         cudaFuncAttributeMaxDynamicSharedMemorySize, ATT2_SMEM);
    attn_kernel2<<<dim3(32, T_SZ / 64), 256, ATT2_SMEM>>>();

    // Proj GEMM (HMMA split-bf16): grid (8, 32)
    gemm_hmma<<<dim3(C_SZ / 128, M_ROWS / 128), 256, GEMM_SMEM>>>(
        c_proj_b, out, 1);
}

// round 4
// speedup vs baseline: 4.0160x; 1.7716x over previous
#include <cuda_runtime.h>
#include <cuda_bf16.h>
#include <cstdint>

#define B_SZ   2
#define T_SZ   2048
#define C_SZ   1024
#define M_ROWS 4096
#define N_QKV  3072
#define GEMM_K 1024

// ---------------------------------------------------------------------------
// Scratch (__device__ globals; no allocation allowed)
// ---------------------------------------------------------------------------
__device__ __nv_bfloat16 g_x_hi[M_ROWS * C_SZ];
__device__ __nv_bfloat16 g_x_lo[M_ROWS * C_SZ];
__device__ __nv_bfloat16 g_wq_hi[N_QKV * GEMM_K];   // transposed [n][k]
__device__ __nv_bfloat16 g_wq_lo[N_QKV * GEMM_K];
__device__ __nv_bfloat16 g_wp_hi[C_SZ * GEMM_K];    // transposed [n][k]
__device__ __nv_bfloat16 g_wp_lo[C_SZ * GEMM_K];
// qkv outputs, split bf16, [bh][t][d]
__device__ __nv_bfloat16 g_kh[32 * T_SZ * 64], g_kl[32 * T_SZ * 64];
__device__ __nv_bfloat16 g_qh[32 * T_SZ * 64], g_ql[32 * T_SZ * 64];
__device__ __nv_bfloat16 g_vh[32 * T_SZ * 64], g_vl[32 * T_SZ * 64];
// attention out, split bf16, [b][t][C]
__device__ __nv_bfloat16 g_ao_hi[M_ROWS * C_SZ], g_ao_lo[M_ROWS * C_SZ];

// ---------------------------------------------------------------------------
// PTX helpers (plain sm_103 target: no 'a'-suffix features)
// ---------------------------------------------------------------------------
#define CP_ASYNC16(dst, src) \
    asm volatile("cp.async.cg.shared.global [%0], [%1], 16;" :: "r"(dst), "l"(src))
#define CP_COMMIT() asm volatile("cp.async.commit_group;" ::: "memory")
#define CP_WAIT1()  asm volatile("cp.async.wait_group 1;" ::: "memory")
#define CP_WAIT0()  asm volatile("cp.async.wait_group 0;" ::: "memory")

__device__ __forceinline__ void ldm_x4(uint32_t* r, uint32_t a) {
    asm volatile("ldmatrix.sync.aligned.m8n8.x4.shared.b16 {%0,%1,%2,%3}, [%4];"
                 : "=r"(r[0]), "=r"(r[1]), "=r"(r[2]), "=r"(r[3]) : "r"(a));
}
__device__ __forceinline__ void ldm_x4t(uint32_t* r, uint32_t a) {
    asm volatile("ldmatrix.sync.aligned.m8n8.x4.trans.shared.b16 {%0,%1,%2,%3}, [%4];"
                 : "=r"(r[0]), "=r"(r[1]), "=r"(r[2]), "=r"(r[3]) : "r"(a));
}
__device__ __forceinline__ void mma_bf16(float* d, const uint32_t* a,
                                         const uint32_t* b) {
    asm volatile(
        "mma.sync.aligned.m16n8k16.row.col.f32.bf16.bf16.f32 "
        "{%0,%1,%2,%3}, {%4,%5,%6,%7}, {%8,%9}, {%0,%1,%2,%3};"
        : "+f"(d[0]), "+f"(d[1]), "+f"(d[2]), "+f"(d[3])
        : "r"(a[0]), "r"(a[1]), "r"(a[2]), "r"(a[3]), "r"(b[0]), "r"(b[1]));
}
__device__ __forceinline__ uint32_t packbf(float lo, float hi) {
    __nv_bfloat162 t = __floats2bfloat162_rn(lo, hi);
    return *reinterpret_cast<uint32_t*>(&t);
}
__device__ __forceinline__ float lowf(uint32_t u)  { return __uint_as_float(u << 16); }
__device__ __forceinline__ float highf(uint32_t u) { return __uint_as_float(u & 0xFFFF0000u); }

// ---------------------------------------------------------------------------
// Prep: fp32 -> (hi, lo) bf16
// ---------------------------------------------------------------------------
__global__ __launch_bounds__(256)
void split_x_kernel(const float* __restrict__ in) {
    int i = blockIdx.x * 256 + threadIdx.x;
    float v = in[i];
    __nv_bfloat16 h = __float2bfloat16(v);
    g_x_hi[i] = h;
    g_x_lo[i] = __float2bfloat16(v - __bfloat162float(h));
}

__global__ void tsplit_kernel(const float* __restrict__ w, int N, int mode) {
    __shared__ float tile[32][33];
    const int nb = blockIdx.x * 32, kb = blockIdx.y * 32;
    const int tx = threadIdx.x, ty = threadIdx.y;   // (32, 8)
#pragma unroll
    for (int i2 = 0; i2 < 32; i2 += 8)
        tile[ty + i2][tx] = w[(size_t)(kb + ty + i2) * N + nb + tx];
    __syncthreads();
    __nv_bfloat16* oh = mode ? g_wp_hi : g_wq_hi;
    __nv_bfloat16* ol = mode ? g_wp_lo : g_wq_lo;
#pragma unroll
    for (int i2 = 0; i2 < 32; i2 += 8) {
        float v = tile[tx][ty + i2];
        __nv_bfloat16 h = __float2bfloat16(v);
        size_t o = (size_t)(nb + ty + i2) * GEMM_K + kb + tx;
        oh[o] = h;
        ol[o] = __float2bfloat16(v - __bfloat162float(h));
    }
}

// ---------------------------------------------------------------------------
// HMMA split-bf16 GEMM, 128x128 tile, BK=32, 3-stage cp.async pipeline.
// mode 0: epilogue bias + split-write into g_{k,q,v}{h,l}  [bh][t][d]
// mode 1: epilogue bias + fp32 store to out
// ---------------------------------------------------------------------------
#define TILE_B   10240                 // 128 rows * 80 B
#define STAGE_B  (4 * TILE_B)          // 40960
#define GEMM_SMEM (3 * STAGE_B)        // 122880

__global__ __launch_bounds__(256, 1)
void gemm_hmma(const float* __restrict__ bias, float* __restrict__ out,
               int mode) {
    extern __shared__ char smem[];
    const uint32_t sbase = (uint32_t)__cvta_generic_to_shared(smem);
    const int tid = threadIdx.x;
    const int lane = tid & 31, warp = tid >> 5;
    const int wr = warp & 3, wc = warp >> 2;
    const int rowBase = blockIdx.y * 128;
    const int colBase = blockIdx.x * 128;

    const __nv_bfloat16 *srcs[4];
    if (mode == 0) { srcs[0] = g_x_hi;  srcs[1] = g_x_lo;  srcs[2] = g_wq_hi; srcs[3] = g_wq_lo; }
    else           { srcs[0] = g_ao_hi; srcs[1] = g_ao_lo; srcs[2] = g_wp_hi; srcs[3] = g_wp_lo; }
    const int bases[4] = {rowBase, rowBase, colBase, colBase};

    float acc[2][8][4];
#pragma unroll
    for (int mt = 0; mt < 2; mt++)
#pragma unroll
        for (int nt = 0; nt < 8; nt++)
#pragma unroll
            for (int q = 0; q < 4; q++) acc[mt][nt][q] = 0.f;

    auto prefetch = [&](int chunk) {
        const int st = chunk % 3;
        const int k0 = chunk * 32;
#pragma unroll
        for (int w = 0; w < 4; w++) {
#pragma unroll
            for (int it = 0; it < 2; it++) {
                int p = tid + it * 256;            // 0..511
                int r = p >> 2, cp = p & 3;
                const __nv_bfloat16* g =
                    srcs[w] + (size_t)(bases[w] + r) * GEMM_K + k0 + cp * 8;
                uint32_t d = sbase + (uint32_t)(st * STAGE_B + w * TILE_B
                                                + r * 80 + cp * 16);
                CP_ASYNC16(d, g);
            }
        }
        CP_COMMIT();
    };

    prefetch(0);
    prefetch(1);

    const int NC = GEMM_K / 32;          // 32
    for (int c = 0; c < NC; c++) {
        if (c == NC - 1) { CP_WAIT0(); } else { CP_WAIT1(); }
        __syncthreads();
        if (c + 2 < NC) prefetch(c + 2);

        const uint32_t bufBase = sbase + (uint32_t)((c % 3) * STAGE_B);
        const uint32_t ahB = bufBase;
        const uint32_t alB = bufBase + TILE_B;
        const uint32_t bhB = bufBase + 2 * TILE_B;
        const uint32_t blB = bufBase + 3 * TILE_B;

#pragma unroll
        for (int s = 0; s < 2; s++) {
            uint32_t ah[2][4], al[2][4], bh[4][4], bl[4][4];
            const int akb = s * 32 + ((lane >> 4) & 1) * 16;
            const int arow = wr * 32 + (lane & 7) + ((lane >> 3) & 1) * 8;
            ldm_x4(ah[0], ahB + (uint32_t)(arow * 80 + akb));
            ldm_x4(ah[1], ahB + (uint32_t)((arow + 16) * 80 + akb));
            ldm_x4(al[0], alB + (uint32_t)(arow * 80 + akb));
            ldm_x4(al[1], alB + (uint32_t)((arow + 16) * 80 + akb));

            const int bkb = s * 32 + ((lane >> 3) & 1) * 16;
            const int brow = wc * 64 + ((lane >> 4) & 1) * 8 + (lane & 7);
#pragma unroll
            for (int p2 = 0; p2 < 4; p2++) {
                ldm_x4(bh[p2], bhB + (uint32_t)((brow + p2 * 16) * 80 + bkb));
                ldm_x4(bl[p2], blB + (uint32_t)((brow + p2 * 16) * 80 + bkb));
            }

#pragma unroll
            for (int mt = 0; mt < 2; mt++)
#pragma unroll
                for (int nt = 0; nt < 8; nt++) {
                    const uint32_t* bhf = &bh[nt >> 1][(nt & 1) * 2];
                    const uint32_t* blf = &bl[nt >> 1][(nt & 1) * 2];
                    mma_bf16(acc[mt][nt], ah[mt], bhf);
                    mma_bf16(acc[mt][nt], ah[mt], blf);
                    mma_bf16(acc[mt][nt], al[mt], bhf);
                }
        }
    }

    const int r0 = lane >> 2;
    const int c0 = (lane & 3) * 2;
#pragma unroll
    for (int mt = 0; mt < 2; mt++) {
#pragma unroll
        for (int nt = 0; nt < 8; nt++) {
            const int n0 = colBase + wc * 64 + nt * 8 + c0;
            const float b0 = bias[n0], b1 = bias[n0 + 1];
#pragma unroll
            for (int half = 0; half < 2; half++) {
                const int m = rowBase + wr * 32 + mt * 16 + r0 + half * 8;
                float f0 = acc[mt][nt][half * 2 + 0] + b0;
                float f1 = acc[mt][nt][half * 2 + 1] + b1;
                if (mode == 0) {
                    const int bb = m >> 11, t = m & 2047;
                    const int sec = n0 >> 10, cc = n0 & 1023;
                    const int h = cc >> 6, d0 = cc & 63;
                    __nv_bfloat16* dh = (sec == 0 ? g_kh : sec == 1 ? g_qh : g_vh);
                    __nv_bfloat16* dl = (sec == 0 ? g_kl : sec == 1 ? g_ql : g_vl);
                    size_t off = (((size_t)(bb * 16 + h)) * T_SZ + t) * 64 + d0;
                    uint32_t hi = packbf(f0, f1);
                    uint32_t lo = packbf(f0 - lowf(hi), f1 - highf(hi));
                    *(uint32_t*)(dh + off) = hi;
                    *(uint32_t*)(dl + off) = lo;
                } else {
                    float2 v; v.x = f0; v.y = f1;
                    *(float2*)(out + (size_t)m * C_SZ + n0) = v;
                }
            }
        }
    }
}

// ---------------------------------------------------------------------------
// Flash attention, split-bf16 HMMA. Source convention wei = K@Q^T:
// query-role = k-section (g_kh/g_kl), key-role = q-section (g_qh/g_ql).
// Block: one (b,h), 128 i-rows, 8 warps x 16 rows. j-tiles of 64, causal.
// ---------------------------------------------------------------------------
#define AST   144                      // smem row stride bytes (64 bf16 + pad)
#define SQH_O 0
#define SQL_O (128 * AST)              // 18432
#define SKV_O (2 * 128 * AST)          // 36864
#define KVVAR (64 * AST)               // 9216 per variant
#define KVBUF (4 * KVVAR)              // 36864 per buffer
#define ATT_SMEM (SKV_O + 2 * KVBUF)   // 110592

__global__ __launch_bounds__(256, 1)
void attn_hmma() {
    extern __shared__ char smem[];
    const uint32_t sbase = (uint32_t)__cvta_generic_to_shared(smem);
    const int tid = threadIdx.x;
    const int lane = tid & 31, w = tid >> 5;
    const int bh = blockIdx.x;
    const int it = (int)(gridDim.y - 1 - blockIdx.y);   // heavy blocks first

    const size_t hb = (size_t)bh * T_SZ * 64;
    const __nv_bfloat16* roleQh = g_kh + hb;    // query-role = k
    const __nv_bfloat16* roleQl = g_kl + hb;
    const __nv_bfloat16* kvsrc[4] = {g_qh + hb, g_ql + hb, g_vh + hb, g_vl + hb};

    auto prefetchKV = [&](int jt) {
        const int buf = jt & 1;
#pragma unroll
        for (int i = 0; i < 8; i++) {
            int p = tid + i * 256;               // 0..2047
            int v = p >> 9, rem = p & 511;
            int r = rem >> 3, cp = rem & 7;
            const __nv_bfloat16* src = kvsrc[v] + (size_t)(jt * 64 + r) * 64 + cp * 8;
            uint32_t dst = sbase + (uint32_t)(SKV_O + buf * KVBUF + v * KVVAR
                                              + r * AST + cp * 16);
            CP_ASYNC16(dst, src);
        }
        CP_COMMIT();
    };

    prefetchKV(0);

    // Q tile, scaled by 1/8 (exact in bf16 for both hi and lo parts)
    {
        const __nv_bfloat162 sc = __floats2bfloat162_rn(0.125f, 0.125f);
        for (int p = tid; p < 128 * 32; p += 256) {
            int r = p >> 5, c2 = p & 31;
            size_t go = (size_t)(it * 128 + r) * 64 + c2 * 2;
            __nv_bfloat162 vh = *(const __nv_bfloat162*)(roleQh + go);
            __nv_bfloat162 vl = *(const __nv_bfloat162*)(roleQl + go);
            *(__nv_bfloat162*)(smem + SQH_O + r * AST + c2 * 4) = __hmul2(vh, sc);
            *(__nv_bfloat162*)(smem + SQL_O + r * AST + c2 * 4) = __hmul2(vl, sc);
        }
    }
    __syncthreads();

    // Hoist Q A-fragments (persist across the whole j loop)
    uint32_t ah[4][4], al[4][4];
    {
        const int arow = w * 16 + (lane & 7) + ((lane >> 3) & 1) * 8;
        const int ab = ((lane >> 4) & 1) * 16;
#pragma unroll
        for (int kk = 0; kk < 4; kk++) {
            ldm_x4(ah[kk], sbase + (uint32_t)(SQH_O + arow * AST + kk * 32 + ab));
            ldm_x4(al[kk], sbase + (uint32_t)(SQL_O + arow * AST + kk * 32 + ab));
        }
    }

    float m0 = -1e30f, m1 = -1e30f, l0 = 0.f, l1 = 0.f;
    float O[8][4];
#pragma unroll
    for (int dt = 0; dt < 8; dt++)
#pragma unroll
        for (int q = 0; q < 4; q++) O[dt][q] = 0.f;

    const int iwmin = it * 128 + w * 16;
    const int jlast = 2 * it + 1;

    for (int jt = 0; jt <= jlast; jt++) {
        CP_WAIT0();
        __syncthreads();
        if (jt < jlast) prefetchKV(jt + 1);

        if (jt * 64 <= iwmin + 15) {                 // warp has unmasked work
            const uint32_t kb = sbase + (uint32_t)(SKV_O + (jt & 1) * KVBUF);
            float s[8][4];
#pragma unroll
            for (int nt = 0; nt < 8; nt++)
#pragma unroll
                for (int q = 0; q < 4; q++) s[nt][q] = 0.f;

            // ---- scores: S = Qs @ K^T (3-pass split) ----
#pragma unroll
            for (int kk = 0; kk < 4; kk++) {
                const int bb = kk * 32 + ((lane >> 3) & 1) * 16;
                const int br = ((lane >> 4) & 1) * 8 + (lane & 7);
#pragma unroll
                for (int np = 0; np < 4; np++) {
                    uint32_t kh4[4], kl4[4];
                    uint32_t a = kb + (uint32_t)((np * 16 + br) * AST + bb);
                    ldm_x4(kh4, a);
                    ldm_x4(kl4, a + KVVAR);
                    mma_bf16(s[2 * np],     ah[kk], kh4 + 0);
                    mma_bf16(s[2 * np],     ah[kk], kl4 + 0);
                    mma_bf16(s[2 * np],     al[kk], kh4 + 0);
                    mma_bf16(s[2 * np + 1], ah[kk], kh4 + 2);
                    mma_bf16(s[2 * np + 1], ah[kk], kl4 + 2);
                    mma_bf16(s[2 * np + 1], al[kk], kh4 + 2);
                }
            }

            const int i0 = iwmin + (lane >> 2);
            if (jt * 64 + 63 > iwmin) {              // mask needed
#pragma unroll
                for (int nt = 0; nt < 8; nt++)
#pragma unroll
                    for (int q = 0; q < 4; q++) {
                        int j = jt * 64 + nt * 8 + (lane & 3) * 2 + (q & 1);
                        int i = i0 + ((q >> 1) ? 8 : 0);
                        if (j > i) s[nt][q] = -1e30f;
                    }
            }

            // ---- online softmax ----
            float mx0 = -1e30f, mx1 = -1e30f;
#pragma unroll
            for (int nt = 0; nt < 8; nt++) {
                mx0 = fmaxf(mx0, fmaxf(s[nt][0], s[nt][1]));
                mx1 = fmaxf(mx1, fmaxf(s[nt][2], s[nt][3]));
            }
            mx0 = fmaxf(mx0, __shfl_xor_sync(0xffffffffu, mx0, 1));
            mx0 = fmaxf(mx0, __shfl_xor_sync(0xffffffffu, mx0, 2));
            mx1 = fmaxf(mx1, __shfl_xor_sync(0xffffffffu, mx1, 1));
            mx1 = fmaxf(mx1, __shfl_xor_sync(0xffffffffu, mx1, 2));
            float mn0 = fmaxf(m0, mx0), mn1 = fmaxf(m1, mx1);
            float a0 = __expf(m0 - mn0), a1 = __expf(m1 - mn1);
            float sum0 = 0.f, sum1 = 0.f;
#pragma unroll
            for (int nt = 0; nt < 8; nt++) {
                s[nt][0] = __expf(s[nt][0] - mn0);
                s[nt][1] = __expf(s[nt][1] - mn0);
                s[nt][2] = __expf(s[nt][2] - mn1);
                s[nt][3] = __expf(s[nt][3] - mn1);
                sum0 += s[nt][0] + s[nt][1];
                sum1 += s[nt][2] + s[nt][3];
            }
            sum0 += __shfl_xor_sync(0xffffffffu, sum0, 1);
            sum0 += __shfl_xor_sync(0xffffffffu, sum0, 2);
            sum1 += __shfl_xor_sync(0xffffffffu, sum1, 1);
            sum1 += __shfl_xor_sync(0xffffffffu, sum1, 2);
            l0 = l0 * a0 + sum0;  l1 = l1 * a1 + sum1;
            m0 = mn0;             m1 = mn1;
#pragma unroll
            for (int dt = 0; dt < 8; dt++) {
                O[dt][0] *= a0; O[dt][1] *= a0;
                O[dt][2] *= a1; O[dt][3] *= a1;
            }

            // ---- PV: O += P @ V (3-pass split, P from fragment regs) ----
#pragma unroll
            for (int kk = 0; kk < 4; kk++) {
                uint32_t pah[4], pal[4];
#pragma unroll
                for (int t = 0; t < 4; t++) {
                    float f0 = s[2 * kk + (t >> 1)][(t & 1) * 2 + 0];
                    float f1 = s[2 * kk + (t >> 1)][(t & 1) * 2 + 1];
                    pah[t] = packbf(f0, f1);
                    pal[t] = packbf(f0 - lowf(pah[t]), f1 - highf(pah[t]));
                }
                const int vrow = kk * 16 + (lane & 7) + ((lane >> 3) & 1) * 8;
                const int voff = ((lane >> 4) & 1) * 16;
#pragma unroll
                for (int dp = 0; dp < 4; dp++) {
                    uint32_t vh4[4], vl4[4];
                    uint32_t a = kb + (uint32_t)(2 * KVVAR + vrow * AST + dp * 32 + voff);
                    ldm_x4t(vh4, a);
                    ldm_x4t(vl4, a + KVVAR);
                    mma_bf16(O[2 * dp],     pah, vh4 + 0);
                    mma_bf16(O[2 * dp],     pal, vh4 + 0);
                    mma_bf16(O[2 * dp],     pah, vl4 + 0);
                    mma_bf16(O[2 * dp + 1], pah, vh4 + 2);
                    mma_bf16(O[2 * dp + 1], pal, vh4 + 2);
                    mma_bf16(O[2 * dp + 1], pah, vl4 + 2);
                }
            }
        }
    }

    // ---- epilogue: normalize, split to bf16, write [b][t][C] ----
    const float inv0 = 1.f / l0, inv1 = 1.f / l1;
    const int b = bh >> 4, h = bh & 15;
    const int i0 = it * 128 + w * 16 + (lane >> 2);
#pragma unroll
    for (int dt = 0; dt < 8; dt++) {
        const int col = h * 64 + dt * 8 + (lane & 3) * 2;
        {
            float f0 = O[dt][0] * inv0, f1 = O[dt][1] * inv0;
            uint32_t hi = packbf(f0, f1);
            uint32_t lo = packbf(f0 - lowf(hi), f1 - highf(hi));
            size_t off = ((size_t)(b * T_SZ + i0)) * C_SZ + col;
            *(uint32_t*)(g_ao_hi + off) = hi;
            *(uint32_t*)(g_ao_lo + off) = lo;
        }
        {
            float f0 = O[dt][2] * inv1, f1 = O[dt][3] * inv1;
            uint32_t hi = packbf(f0, f1);
            uint32_t lo = packbf(f0 - lowf(hi), f1 - highf(hi));
            size_t off = ((size_t)(b * T_SZ + i0 + 8)) * C_SZ + col;
            *(uint32_t*)(g_ao_hi + off) = hi;
            *(uint32_t*)(g_ao_lo + off) = lo;
        }
    }
}

// ---------------------------------------------------------------------------
extern "C" void kernel_launch(void* const* d_in, const int* in_sizes, int n_in,
                              void* d_out, int out_size) {
    const float* x        = (const float*)d_in[0];
    const float* c_attn_w = (const float*)d_in[1];
    const float* c_attn_b = (const float*)d_in[2];
    const float* c_proj_w = (const float*)d_in[3];
    const float* c_proj_b = (const float*)d_in[4];
    float* out = (float*)d_out;

    split_x_kernel<<<(M_ROWS * C_SZ) / 256, 256>>>(x);
    tsplit_kernel<<<dim3(N_QKV / 32, GEMM_K / 32), dim3(32, 8)>>>(c_attn_w, N_QKV, 0);
    tsplit_kernel<<<dim3(C_SZ / 32, GEMM_K / 32), dim3(32, 8)>>>(c_proj_w, C_SZ, 1);

    cudaFuncSetAttribute(gemm_hmma,
                         cudaFuncAttributeMaxDynamicSharedMemorySize, GEMM_SMEM);
    cudaFuncSetAttribute(attn_hmma,
                         cudaFuncAttributeMaxDynamicSharedMemorySize, ATT_SMEM);

    gemm_hmma<<<dim3(N_QKV / 128, M_ROWS / 128), 256, GEMM_SMEM>>>(
        c_attn_b, nullptr, 0);

    attn_hmma<<<dim3(32, T_SZ / 128), 256, ATT_SMEM>>>();

    gemm_hmma<<<dim3(C_SZ / 128, M_ROWS / 128), 256, GEMM_SMEM>>>(
        c_proj_b, out, 1);
}

// round 6
// speedup vs baseline: 4.4138x; 1.0991x over previous
#include <cuda_runtime.h>
#include <cuda_bf16.h>
#include <cstdint>

#define B_SZ   2
#define T_SZ   2048
#define C_SZ   1024
#define M_ROWS 4096
#define N_QKV  3072
#define GEMM_K 1024

// ---------------------------------------------------------------------------
// Scratch (__device__ globals; no allocation allowed)
// ---------------------------------------------------------------------------
__device__ __nv_bfloat16 g_x_hi[M_ROWS * C_SZ];
__device__ __nv_bfloat16 g_x_lo[M_ROWS * C_SZ];
__device__ __nv_bfloat16 g_wq_hi[N_QKV * GEMM_K];   // transposed [n][k]
__device__ __nv_bfloat16 g_wq_lo[N_QKV * GEMM_K];
__device__ __nv_bfloat16 g_wp_hi[C_SZ * GEMM_K];    // transposed [n][k]
__device__ __nv_bfloat16 g_wp_lo[C_SZ * GEMM_K];
// qkv outputs, split bf16, [bh][t][d]
__device__ __nv_bfloat16 g_kh[32 * T_SZ * 64], g_kl[32 * T_SZ * 64];
__device__ __nv_bfloat16 g_qh[32 * T_SZ * 64], g_ql[32 * T_SZ * 64];
__device__ __nv_bfloat16 g_vh[32 * T_SZ * 64], g_vl[32 * T_SZ * 64];
// attention out, split bf16, [b][t][C]
__device__ __nv_bfloat16 g_ao_hi[M_ROWS * C_SZ], g_ao_lo[M_ROWS * C_SZ];

// ---------------------------------------------------------------------------
// PTX helpers (plain sm_103 target)
// ---------------------------------------------------------------------------
#define CP_ASYNC16(dst, src) \
    asm volatile("cp.async.cg.shared.global [%0], [%1], 16;" :: "r"(dst), "l"(src))
#define CP_COMMIT() asm volatile("cp.async.commit_group;" ::: "memory")
#define CP_WAIT1()  asm volatile("cp.async.wait_group 1;" ::: "memory")
#define CP_WAIT0()  asm volatile("cp.async.wait_group 0;" ::: "memory")

__device__ __forceinline__ void ldm_x4(uint32_t* r, uint32_t a) {
    asm volatile("ldmatrix.sync.aligned.m8n8.x4.shared.b16 {%0,%1,%2,%3}, [%4];"
                 : "=r"(r[0]), "=r"(r[1]), "=r"(r[2]), "=r"(r[3]) : "r"(a));
}
__device__ __forceinline__ void ldm_x4t(uint32_t* r, uint32_t a) {
    asm volatile("ldmatrix.sync.aligned.m8n8.x4.trans.shared.b16 {%0,%1,%2,%3}, [%4];"
                 : "=r"(r[0]), "=r"(r[1]), "=r"(r[2]), "=r"(r[3]) : "r"(a));
}
__device__ __forceinline__ void mma_bf16(float* d, const uint32_t* a,
                                         const uint32_t* b) {
    asm volatile(
        "mma.sync.aligned.m16n8k16.row.col.f32.bf16.bf16.f32 "
        "{%0,%1,%2,%3}, {%4,%5,%6,%7}, {%8,%9}, {%0,%1,%2,%3};"
        : "+f"(d[0]), "+f"(d[1]), "+f"(d[2]), "+f"(d[3])
        : "r"(a[0]), "r"(a[1]), "r"(a[2]), "r"(a[3]), "r"(b[0]), "r"(b[1]));
}
__device__ __forceinline__ uint32_t packbf(float lo, float hi) {
    __nv_bfloat162 t = __floats2bfloat162_rn(lo, hi);
    return *reinterpret_cast<uint32_t*>(&t);
}
__device__ __forceinline__ float lowf(uint32_t u)  { return __uint_as_float(u << 16); }
__device__ __forceinline__ float highf(uint32_t u) { return __uint_as_float(u & 0xFFFF0000u); }

// ---------------------------------------------------------------------------
// Prep: fp32 -> (hi, lo) bf16
// ---------------------------------------------------------------------------
__global__ __launch_bounds__(256)
void split_x_kernel(const float* __restrict__ in) {
    int i = blockIdx.x * 256 + threadIdx.x;
    float v = in[i];
    __nv_bfloat16 h = __float2bfloat16(v);
    g_x_hi[i] = h;
    g_x_lo[i] = __float2bfloat16(v - __bfloat162float(h));
}

__global__ void tsplit_kernel(const float* __restrict__ w, int N, int mode) {
    __shared__ float tile[32][33];
    const int nb = blockIdx.x * 32, kb = blockIdx.y * 32;
    const int tx = threadIdx.x, ty = threadIdx.y;   // (32, 8)
#pragma unroll
    for (int i2 = 0; i2 < 32; i2 += 8)
        tile[ty + i2][tx] = w[(size_t)(kb + ty + i2) * N + nb + tx];
    __syncthreads();
    __nv_bfloat16* oh = mode ? g_wp_hi : g_wq_hi;
    __nv_bfloat16* ol = mode ? g_wp_lo : g_wq_lo;
#pragma unroll
    for (int i2 = 0; i2 < 32; i2 += 8) {
        float v = tile[tx][ty + i2];
        __nv_bfloat16 h = __float2bfloat16(v);
        size_t o = (size_t)(nb + ty + i2) * GEMM_K + kb + tx;
        oh[o] = h;
        ol[o] = __float2bfloat16(v - __bfloat162float(h));
    }
}

// ---------------------------------------------------------------------------
// HMMA split-bf16 GEMM, 128x128 tile, BK=64, 3-stage cp.async pipeline,
// register double-buffered ldmatrix fragments (LDSM overlaps HMMA).
// Pipeline ordering (race-free): WAIT -> syncthreads -> prefetch(c+2).
// mode 0: epilogue bias + split-write into g_{k,q,v}{h,l}  [bh][t][d]
// mode 1: epilogue bias + fp32 store to out
// ---------------------------------------------------------------------------
#define G_ROWB   144                     // 128B data + 16B pad
#define G_TILE   (128 * G_ROWB)          // 18432 per variant
#define G_STAGE  (4 * G_TILE)            // 73728
#define GEMM_SMEM (3 * G_STAGE)          // 221184

struct GFrags {
    uint32_t ah[2][4], al[2][4], bh[4][4], bl[4][4];
};

__device__ __forceinline__ void g_load_frags(GFrags& F, uint32_t bufBase,
                                             int s, int wr, int wc, int lane) {
    const int akb = s * 32 + ((lane >> 4) & 1) * 16;
    const int arow = wr * 32 + (lane & 7) + ((lane >> 3) & 1) * 8;
    ldm_x4(F.ah[0], bufBase + (uint32_t)(arow * G_ROWB + akb));
    ldm_x4(F.ah[1], bufBase + (uint32_t)((arow + 16) * G_ROWB + akb));
    ldm_x4(F.al[0], bufBase + (uint32_t)(G_TILE + arow * G_ROWB + akb));
    ldm_x4(F.al[1], bufBase + (uint32_t)(G_TILE + (arow + 16) * G_ROWB + akb));
    const int bkb = s * 32 + ((lane >> 3) & 1) * 16;
    const int brow = wc * 64 + ((lane >> 4) & 1) * 8 + (lane & 7);
#pragma unroll
    for (int p2 = 0; p2 < 4; p2++) {
        ldm_x4(F.bh[p2], bufBase + (uint32_t)(2 * G_TILE + (brow + p2 * 16) * G_ROWB + bkb));
        ldm_x4(F.bl[p2], bufBase + (uint32_t)(3 * G_TILE + (brow + p2 * 16) * G_ROWB + bkb));
    }
}

__device__ __forceinline__ void g_mma_all(float acc[2][8][4], const GFrags& F) {
#pragma unroll
    for (int mt = 0; mt < 2; mt++)
#pragma unroll
        for (int nt = 0; nt < 8; nt++) {
            const uint32_t* bhf = &F.bh[nt >> 1][(nt & 1) * 2];
            const uint32_t* blf = &F.bl[nt >> 1][(nt & 1) * 2];
            mma_bf16(acc[mt][nt], F.ah[mt], bhf);
            mma_bf16(acc[mt][nt], F.ah[mt], blf);
            mma_bf16(acc[mt][nt], F.al[mt], bhf);
        }
}

__global__ __launch_bounds__(256, 1)
void gemm_hmma(const float* __restrict__ bias, float* __restrict__ out,
               int mode) {
    extern __shared__ char smem[];
    const uint32_t sbase = (uint32_t)__cvta_generic_to_shared(smem);
    const int tid = threadIdx.x;
    const int lane = tid & 31, warp = tid >> 5;
    const int wr = warp & 3, wc = warp >> 2;
    const int rowBase = blockIdx.y * 128;
    const int colBase = blockIdx.x * 128;

    const __nv_bfloat16 *srcs[4];
    if (mode == 0) { srcs[0] = g_x_hi;  srcs[1] = g_x_lo;  srcs[2] = g_wq_hi; srcs[3] = g_wq_lo; }
    else           { srcs[0] = g_ao_hi; srcs[1] = g_ao_lo; srcs[2] = g_wp_hi; srcs[3] = g_wp_lo; }
    const int bases[4] = {rowBase, rowBase, colBase, colBase};

    float acc[2][8][4];
#pragma unroll
    for (int mt = 0; mt < 2; mt++)
#pragma unroll
        for (int nt = 0; nt < 8; nt++)
#pragma unroll
            for (int q = 0; q < 4; q++) acc[mt][nt][q] = 0.f;

    // per chunk: 4 variants x 128 rows x 128B = 64KB; thread does 16x 16B
    auto prefetch = [&](int chunk) {
        const int st = chunk % 3;
        const int k0 = chunk * 64;
#pragma unroll
        for (int w = 0; w < 4; w++) {
#pragma unroll
            for (int it = 0; it < 4; it++) {
                int p = tid + it * 256;            // 0..1023
                int r = p >> 3, cp = p & 7;
                const __nv_bfloat16* g =
                    srcs[w] + (size_t)(bases[w] + r) * GEMM_K + k0 + cp * 8;
                uint32_t d = sbase + (uint32_t)(st * G_STAGE + w * G_TILE
                                                + r * G_ROWB + cp * 16);
                CP_ASYNC16(d, g);
            }
        }
        CP_COMMIT();
    };

    prefetch(0);
    prefetch(1);

    GFrags F0, F1;
    const int NC = GEMM_K / 64;          // 16
    for (int c = 0; c < NC; c++) {
        if (c + 1 < NC) { CP_WAIT1(); } else { CP_WAIT0(); }
        __syncthreads();
        if (c + 2 < NC) prefetch(c + 2);   // overwrites stage (c-1)%3: safe, all
                                           // warps passed the barrier above

        const uint32_t bufBase = sbase + (uint32_t)((c % 3) * G_STAGE);
        g_load_frags(F0, bufBase, 0, wr, wc, lane);
        g_load_frags(F1, bufBase, 1, wr, wc, lane);   // in flight during s=0 MMAs
        g_mma_all(acc, F0);
        g_load_frags(F0, bufBase, 2, wr, wc, lane);
        g_mma_all(acc, F1);
        g_load_frags(F1, bufBase, 3, wr, wc, lane);
        g_mma_all(acc, F0);
        g_mma_all(acc, F1);
    }

    const int r0 = lane >> 2;
    const int c0 = (lane & 3) * 2;
#pragma unroll
    for (int mt = 0; mt < 2; mt++) {
#pragma unroll
        for (int nt = 0; nt < 8; nt++) {
            const int n0 = colBase + wc * 64 + nt * 8 + c0;
            const float b0 = bias[n0], b1 = bias[n0 + 1];
#pragma unroll
            for (int half = 0; half < 2; half++) {
                const int m = rowBase + wr * 32 + mt * 16 + r0 + half * 8;
                float f0 = acc[mt][nt][half * 2 + 0] + b0;
                float f1 = acc[mt][nt][half * 2 + 1] + b1;
                if (mode == 0) {
                    const int bb = m >> 11, t = m & 2047;
                    const int sec = n0 >> 10, cc = n0 & 1023;
                    const int h = cc >> 6, d0 = cc & 63;
                    __nv_bfloat16* dh = (sec == 0 ? g_kh : sec == 1 ? g_qh : g_vh);
                    __nv_bfloat16* dl = (sec == 0 ? g_kl : sec == 1 ? g_ql : g_vl);
                    size_t off = (((size_t)(bb * 16 + h)) * T_SZ + t) * 64 + d0;
                    uint32_t hi = packbf(f0, f1);
                    uint32_t lo = packbf(f0 - lowf(hi), f1 - highf(hi));
                    *(uint32_t*)(dh + off) = hi;
                    *(uint32_t*)(dl + off) = lo;
                } else {
                    float2 v; v.x = f0; v.y = f1;
                    *(float2*)(out + (size_t)m * C_SZ + n0) = v;
                }
            }
        }
    }
}

// ---------------------------------------------------------------------------
// Flash attention, split-bf16 HMMA (unchanged; passed at rel_err 9.4e-6).
// Source convention wei = K@Q^T: query-role = k-section, key-role = q-section.
// ---------------------------------------------------------------------------
#define AST   144
#define SQH_O 0
#define SQL_O (128 * AST)
#define SKV_O (2 * 128 * AST)
#define KVVAR (64 * AST)
#define KVBUF (4 * KVVAR)
#define ATT_SMEM (SKV_O + 2 * KVBUF)   // 110592

__global__ __launch_bounds__(256, 1)
void attn_hmma() {
    extern __shared__ char smem[];
    const uint32_t sbase = (uint32_t)__cvta_generic_to_shared(smem);
    const int tid = threadIdx.x;
    const int lane = tid & 31, w = tid >> 5;
    const int bh = blockIdx.x;
    const int it = (int)(gridDim.y - 1 - blockIdx.y);

    const size_t hb = (size_t)bh * T_SZ * 64;
    const __nv_bfloat16* roleQh = g_kh + hb;
    const __nv_bfloat16* roleQl = g_kl + hb;
    const __nv_bfloat16* kvsrc[4] = {g_qh + hb, g_ql + hb, g_vh + hb, g_vl + hb};

    auto prefetchKV = [&](int jt) {
        const int buf = jt & 1;
#pragma unroll
        for (int i = 0; i < 8; i++) {
            int p = tid + i * 256;
            int v = p >> 9, rem = p & 511;
            int r = rem >> 3, cp = rem & 7;
            const __nv_bfloat16* src = kvsrc[v] + (size_t)(jt * 64 + r) * 64 + cp * 8;
            uint32_t dst = sbase + (uint32_t)(SKV_O + buf * KVBUF + v * KVVAR
                                              + r * AST + cp * 16);
            CP_ASYNC16(dst, src);
        }
        CP_COMMIT();
    };

    prefetchKV(0);

    {
        const __nv_bfloat162 sc = __floats2bfloat162_rn(0.125f, 0.125f);
        for (int p = tid; p < 128 * 32; p += 256) {
            int r = p >> 5, c2 = p & 31;
            size_t go = (size_t)(it * 128 + r) * 64 + c2 * 2;
            __nv_bfloat162 vh = *(const __nv_bfloat162*)(roleQh + go);
            __nv_bfloat162 vl = *(const __nv_bfloat162*)(roleQl + go);
            *(__nv_bfloat162*)(smem + SQH_O + r * AST + c2 * 4) = __hmul2(vh, sc);
            *(__nv_bfloat162*)(smem + SQL_O + r * AST + c2 * 4) = __hmul2(vl, sc);
        }
    }
    __syncthreads();

    uint32_t ah[4][4], al[4][4];
    {
        const int arow = w * 16 + (lane & 7) + ((lane >> 3) & 1) * 8;
        const int ab = ((lane >> 4) & 1) * 16;
#pragma unroll
        for (int kk = 0; kk < 4; kk++) {
            ldm_x4(ah[kk], sbase + (uint32_t)(SQH_O + arow * AST + kk * 32 + ab));
            ldm_x4(al[kk], sbase + (uint32_t)(SQL_O + arow * AST + kk * 32 + ab));
        }
    }

    float m0 = -1e30f, m1 = -1e30f, l0 = 0.f, l1 = 0.f;
    float O[8][4];
#pragma unroll
    for (int dt = 0; dt < 8; dt++)
#pragma unroll
        for (int q = 0; q < 4; q++) O[dt][q] = 0.f;

    const int iwmin = it * 128 + w * 16;
    const int jlast = 2 * it + 1;

    for (int jt = 0; jt <= jlast; jt++) {
        CP_WAIT0();
        __syncthreads();
        if (jt < jlast) prefetchKV(jt + 1);

        if (jt * 64 <= iwmin + 15) {
            const uint32_t kb = sbase + (uint32_t)(SKV_O + (jt & 1) * KVBUF);
            float s[8][4];
#pragma unroll
            for (int nt = 0; nt < 8; nt++)
#pragma unroll
                for (int q = 0; q < 4; q++) s[nt][q] = 0.f;

#pragma unroll
            for (int kk = 0; kk < 4; kk++) {
                const int bb = kk * 32 + ((lane >> 3) & 1) * 16;
                const int br = ((lane >> 4) & 1) * 8 + (lane & 7);
#pragma unroll
                for (int np = 0; np < 4; np++) {
                    uint32_t kh4[4], kl4[4];
                    uint32_t a = kb + (uint32_t)((np * 16 + br) * AST + bb);
                    ldm_x4(kh4, a);
                    ldm_x4(kl4, a + KVVAR);
                    mma_bf16(s[2 * np],     ah[kk], kh4 + 0);
                    mma_bf16(s[2 * np],     ah[kk], kl4 + 0);
                    mma_bf16(s[2 * np],     al[kk], kh4 + 0);
                    mma_bf16(s[2 * np + 1], ah[kk], kh4 + 2);
                    mma_bf16(s[2 * np + 1], ah[kk], kl4 + 2);
                    mma_bf16(s[2 * np + 1], al[kk], kh4 + 2);
                }
            }

            const int i0 = iwmin + (lane >> 2);
            if (jt * 64 + 63 > iwmin) {
#pragma unroll
                for (int nt = 0; nt < 8; nt++)
#pragma unroll
                    for (int q = 0; q < 4; q++) {
                        int j = jt * 64 + nt * 8 + (lane & 3) * 2 + (q & 1);
                        int i = i0 + ((q >> 1) ? 8 : 0);
                        if (j > i) s[nt][q] = -1e30f;
                    }
            }

            float mx0 = -1e30f, mx1 = -1e30f;
#pragma unroll
            for (int nt = 0; nt < 8; nt++) {
                mx0 = fmaxf(mx0, fmaxf(s[nt][0], s[nt][1]));
                mx1 = fmaxf(mx1, fmaxf(s[nt][2], s[nt][3]));
            }
            mx0 = fmaxf(mx0, __shfl_xor_sync(0xffffffffu, mx0, 1));
            mx0 = fmaxf(mx0, __shfl_xor_sync(0xffffffffu, mx0, 2));
            mx1 = fmaxf(mx1, __shfl_xor_sync(0xffffffffu, mx1, 1));
            mx1 = fmaxf(mx1, __shfl_xor_sync(0xffffffffu, mx1, 2));
            float mn0 = fmaxf(m0, mx0), mn1 = fmaxf(m1, mx1);
            float a0 = __expf(m0 - mn0), a1 = __expf(m1 - mn1);
            float sum0 = 0.f, sum1 = 0.f;
#pragma unroll
            for (int nt = 0; nt < 8; nt++) {
                s[nt][0] = __expf(s[nt][0] - mn0);
                s[nt][1] = __expf(s[nt][1] - mn0);
                s[nt][2] = __expf(s[nt][2] - mn1);
                s[nt][3] = __expf(s[nt][3] - mn1);
                sum0 += s[nt][0] + s[nt][1];
                sum1 += s[nt][2] + s[nt][3];
            }
            sum0 += __shfl_xor_sync(0xffffffffu, sum0, 1);
            sum0 += __shfl_xor_sync(0xffffffffu, sum0, 2);
            sum1 += __shfl_xor_sync(0xffffffffu, sum1, 1);
            sum1 += __shfl_xor_sync(0xffffffffu, sum1, 2);
            l0 = l0 * a0 + sum0;  l1 = l1 * a1 + sum1;
            m0 = mn0;             m1 = mn1;
#pragma unroll
            for (int dt = 0; dt < 8; dt++) {
                O[dt][0] *= a0; O[dt][1] *= a0;
                O[dt][2] *= a1; O[dt][3] *= a1;
            }

#pragma unroll
            for (int kk = 0; kk < 4; kk++) {
                uint32_t pah[4], pal[4];
#pragma unroll
                for (int t = 0; t < 4; t++) {
                    float f0 = s[2 * kk + (t >> 1)][(t & 1) * 2 + 0];
                    float f1 = s[2 * kk + (t >> 1)][(t & 1) * 2 + 1];
                    pah[t] = packbf(f0, f1);
                    pal[t] = packbf(f0 - lowf(pah[t]), f1 - highf(pah[t]));
                }
                const int vrow = kk * 16 + (lane & 7) + ((lane >> 3) & 1) * 8;
                const int voff = ((lane >> 4) & 1) * 16;
#pragma unroll
                for (int dp = 0; dp < 4; dp++) {
                    uint32_t vh4[4], vl4[4];
                    uint32_t a = kb + (uint32_t)(2 * KVVAR + vrow * AST + dp * 32 + voff);
                    ldm_x4t(vh4, a);
                    ldm_x4t(vl4, a + KVVAR);
                    mma_bf16(O[2 * dp],     pah, vh4 + 0);
                    mma_bf16(O[2 * dp],     pal, vh4 + 0);
                    mma_bf16(O[2 * dp],     pah, vl4 + 0);
                    mma_bf16(O[2 * dp + 1], pah, vh4 + 2);
                    mma_bf16(O[2 * dp + 1], pal, vh4 + 2);
                    mma_bf16(O[2 * dp + 1], pah, vl4 + 2);
                }
            }
        }
    }

    const float inv0 = 1.f / l0, inv1 = 1.f / l1;
    const int b = bh >> 4, h = bh & 15;
    const int i0 = it * 128 + w * 16 + (lane >> 2);
#pragma unroll
    for (int dt = 0; dt < 8; dt++) {
        const int col = h * 64 + dt * 8 + (lane & 3) * 2;
        {
            float f0 = O[dt][0] * inv0, f1 = O[dt][1] * inv0;
            uint32_t hi = packbf(f0, f1);
            uint32_t lo = packbf(f0 - lowf(hi), f1 - highf(hi));
            size_t off = ((size_t)(b * T_SZ + i0)) * C_SZ + col;
            *(uint32_t*)(g_ao_hi + off) = hi;
            *(uint32_t*)(g_ao_lo + off) = lo;
        }
        {
            float f0 = O[dt][2] * inv1, f1 = O[dt][3] * inv1;
            uint32_t hi = packbf(f0, f1);
            uint32_t lo = packbf(f0 - lowf(hi), f1 - highf(hi));
            size_t off = ((size_t)(b * T_SZ + i0 + 8)) * C_SZ + col;
            *(uint32_t*)(g_ao_hi + off) = hi;
            *(uint32_t*)(g_ao_lo + off) = lo;
        }
    }
}

// ---------------------------------------------------------------------------
extern "C" void kernel_launch(void* const* d_in, const int* in_sizes, int n_in,
                              void* d_out, int out_size) {
    const float* x        = (const float*)d_in[0];
    const float* c_attn_w = (const float*)d_in[1];
    const float* c_attn_b = (const float*)d_in[2];
    const float* c_proj_w = (const float*)d_in[3];
    const float* c_proj_b = (const float*)d_in[4];
    float* out = (float*)d_out;

    split_x_kernel<<<(M_ROWS * C_SZ) / 256, 256>>>(x);
    tsplit_kernel<<<dim3(N_QKV / 32, GEMM_K / 32), dim3(32, 8)>>>(c_attn_w, N_QKV, 0);
    tsplit_kernel<<<dim3(C_SZ / 32, GEMM_K / 32), dim3(32, 8)>>>(c_proj_w, C_SZ, 1);

    cudaFuncSetAttribute(gemm_hmma,
                         cudaFuncAttributeMaxDynamicSharedMemorySize, GEMM_SMEM);
    cudaFuncSetAttribute(attn_hmma,
                         cudaFuncAttributeMaxDynamicSharedMemorySize, ATT_SMEM);

    gemm_hmma<<<dim3(N_QKV / 128, M_ROWS / 128), 256, GEMM_SMEM>>>(
        c_attn_b, nullptr, 0);

    attn_hmma<<<dim3(32, T_SZ / 128), 256, ATT_SMEM>>>();

    gemm_hmma<<<dim3(C_SZ / 128, M_ROWS / 128), 256, GEMM_SMEM>>>(
        c_proj_b, out, 1);
}